// round 7
// baseline (speedup 1.0000x reference)
#include <cuda_runtime.h>
#include <cstdint>

#define BB 4
#define HH 1024
#define WW 1920
#define HW (HH * WW)
#define NPIX (BB * HW)
#define ALPHA 100.0f
#define EPSN 1e-7f

// Interleaved accumulator: [pix][4] = {num_r, num_g, num_b, den}, 16B aligned.
__device__ __align__(16) float g_acc[(size_t)NPIX * 4];
// Interleaved rgb2 for single-line bilinear gather: [B][H][W] x {r,g,b,pad}.
__device__ __align__(16) float4 g_rgb2i[(size_t)NPIX];

__device__ __forceinline__ void red_add_v4(float* addr, float a, float b, float c, float d) {
    asm volatile("red.global.add.v4.f32 [%0], {%1, %2, %3, %4};"
                 :: "l"(addr), "f"(a), "f"(b), "f"(c), "f"(d) : "memory");
}

// ---- Per-batch prologue: planar rgb2 slice -> interleaved float4 (plain loads) ----
__global__ __launch_bounds__(256)
void interleave_kernel(const float* __restrict__ rgb2b, float4* __restrict__ dst) {
    int i = blockIdx.x * 256 + threadIdx.x;
    if (i >= HW) return;
    float4 v;
    v.x = rgb2b[i];
    v.y = rgb2b[i + HW];
    v.z = rgb2b[i + 2 * HW];
    v.w = 0.f;
    dst[i] = v;
}

// ---- Per-batch fused kernel: backwarp metric + exp weight + forward splat ----
// Identical to the 332us anchor except the gather reads interleaved float4.
__global__ __launch_bounds__(256)
void splat_kernel(const float* __restrict__ rgb1b,   // batch slice [3][H][W]
                  const float4* __restrict__ r2i,    // batch slice [H][W]
                  const float* __restrict__ ftgtb,   // batch slice [2][H][W]
                  const float* __restrict__ f12b,    // batch slice [2][H][W]
                  float* __restrict__ metb,          // batch slice of metric out
                  float* __restrict__ accb) {        // batch slice of g_acc
    int rem = blockIdx.x * 256 + threadIdx.x;
    if (rem >= HW) return;
    int y = rem / WW;
    int x = rem - y * WW;

    // ---- backwarp src2 with flow_src1_to_src2 (bilinear gather, zero outside) ----
    float px = (float)x + f12b[rem];
    float py = (float)y + f12b[rem + HW];
    float x0f = floorf(px), y0f = floorf(py);
    int   x0  = (int)x0f,   y0  = (int)y0f;
    float wx = px - x0f, wy = py - y0f;

    float a0 = 0.f, a1 = 0.f, a2 = 0.f;
#pragma unroll
    for (int cy = 0; cy < 2; cy++) {
#pragma unroll
        for (int cx = 0; cx < 2; cx++) {
            int xi = x0 + cx, yi = y0 + cy;
            if (xi >= 0 && xi < WW && yi >= 0 && yi < HH) {
                float w = (cx ? wx : 1.f - wx) * (cy ? wy : 1.f - wy);
                float4 t = __ldg(&r2i[yi * WW + xi]);
                a0 += w * t.x; a1 += w * t.y; a2 += w * t.z;
            }
        }
    }

    float c0 = rgb1b[rem], c1 = rgb1b[rem + HW], c2 = rgb1b[rem + 2 * HW];

    float metric = (fabsf(c0 - a0) + fabsf(c1 - a1) + fabsf(c2 - a2)) * (1.f / 3.f);
    metb[rem] = metric;

    float m  = fmaxf(-ALPHA * metric, -ALPHA);  // upper clip can't trigger (metric>=0)
    float em = expf(m);

    // ---- forward splat with flow_src1_to_tgt (bilinear scatter-add) ----
    px = (float)x + ftgtb[rem];
    py = (float)y + ftgtb[rem + HW];
    x0f = floorf(px); y0f = floorf(py);
    x0 = (int)x0f; y0 = (int)y0f;
    wx = px - x0f; wy = py - y0f;

    float v0 = c0 * em, v1 = c1 * em, v2 = c2 * em;
#pragma unroll
    for (int cy = 0; cy < 2; cy++) {
#pragma unroll
        for (int cx = 0; cx < 2; cx++) {
            int xi = x0 + cx, yi = y0 + cy;
            if (xi >= 0 && xi < WW && yi >= 0 && yi < HH) {
                float w = (cx ? wx : 1.f - wx) * (cy ? wy : 1.f - wy);
                float* p = accb + (size_t)(yi * WW + xi) * 4;
                red_add_v4(p, v0 * w, v1 * w, v2 * w, em * w);
            }
        }
    }
}

// ---- Normalize (identical to anchor) ----
__global__ __launch_bounds__(256)
void norm_kernel(float* __restrict__ out) {
    int idx = blockIdx.x * 256 + threadIdx.x;
    if (idx >= NPIX) return;
    int b   = idx / HW;
    int rem = idx - b * HW;
    float4 acc = *reinterpret_cast<const float4*>(g_acc + (size_t)idx * 4);
    float inv = 1.0f / (acc.w + EPSN);
    float* o = out + (size_t)b * 3 * HW + rem;
    o[0]      = acc.x * inv;
    o[HW]     = acc.y * inv;
    o[2 * HW] = acc.z * inv;
}

extern "C" void kernel_launch(void* const* d_in, const int* in_sizes, int n_in,
                              void* d_out, int out_size) {
    const float* rgb1 = (const float*)d_in[0];
    const float* rgb2 = (const float*)d_in[1];
    const float* ftgt = (const float*)d_in[2];  // flow_src1_to_tgt
    const float* f12  = (const float*)d_in[3];  // flow_src1_to_src2
    float* out = (float*)d_out;

    void* accp = nullptr; void* r2ip = nullptr;
    cudaGetSymbolAddress(&accp, g_acc);
    cudaGetSymbolAddress(&r2ip, g_rgb2i);
    float*  acc = (float*)accp;
    float4* r2i = (float4*)r2ip;

    cudaMemsetAsync(accp, 0, (size_t)NPIX * 4 * sizeof(float));

    int blocks = (HW + 255) / 256;  // 7680
    for (int b = 0; b < BB; b++) {
        const float* rgb2b = rgb2 + (size_t)b * 3 * HW;
        const float* rgb1b = rgb1 + (size_t)b * 3 * HW;
        const float* ftgtb = ftgt + (size_t)b * 2 * HW;
        const float* f12b  = f12  + (size_t)b * 2 * HW;
        float4*      r2ib  = r2i + (size_t)b * HW;
        float*       accb  = acc + (size_t)b * HW * 4;
        float*       metb  = out + (size_t)BB * 3 * HW + (size_t)b * HW;

        interleave_kernel<<<blocks, 256>>>(rgb2b, r2ib);
        splat_kernel<<<blocks, 256>>>(rgb1b, r2ib, ftgtb, f12b, metb, accb);
    }

    norm_kernel<<<(NPIX + 255) / 256, 256>>>(out);
}

// round 8
// speedup vs baseline: 1.3632x; 1.3632x over previous
#include <cuda_runtime.h>
#include <cstdint>

#define BB 4
#define HH 1024
#define WW 1920
#define HW (HH * WW)
#define NPIX (BB * HW)
#define ALPHA 100.0f
#define EPSN 1e-7f

// Interleaved accumulator: [pix][4] = {num_r, num_g, num_b, den}, 16B aligned.
__device__ __align__(16) float g_acc[(size_t)NPIX * 4];

__device__ __forceinline__ void red_add_v4(float* addr, float a, float b, float c, float d) {
    asm volatile("red.global.add.v4.f32 [%0], {%1, %2, %3, %4};"
                 :: "l"(addr), "f"(a), "f"(b), "f"(c), "f"(d) : "memory");
}

__global__ __launch_bounds__(256)
void splat_kernel(const float* __restrict__ rgb1,
                  const float* __restrict__ rgb2,
                  const float* __restrict__ ftgt,
                  const float* __restrict__ f12,
                  float* __restrict__ out) {
    int idx = blockIdx.x * blockDim.x + threadIdx.x;
    if (idx >= NPIX) return;
    int b   = idx / HW;
    int rem = idx - b * HW;
    int y   = rem / WW;
    int x   = rem - y * WW;

    // ---- backwarp src2 with flow_src1_to_src2 (bilinear gather, zero outside) ----
    const float* fl = f12 + (size_t)b * 2 * HW + rem;
    float px = (float)x + fl[0];
    float py = (float)y + fl[HW];
    float x0f = floorf(px), y0f = floorf(py);
    int   x0  = (int)x0f,   y0  = (int)y0f;
    float wx = px - x0f, wy = py - y0f;

    // x-pair merge: one aligned float2 covers (base, base+1); odd x0 needs a
    // scalar fixup for x0+1 (same cache line 15/16 of the time).
    bool ev   = !(x0 & 1);
    int  base = x0 & ~1;                        // even (negative-safe: -1&~1=-2)
    bool bx   = (base >= 0) && (base < WW);     // base even, WW even -> base<=WW-2
    int  xb   = base + 2;                       // == x0+1 when x0 odd
    bool fixv = (xb >= 0) && (xb < WW);

    const float* r2 = rgb2 + (size_t)b * 3 * HW;
    float a0 = 0.f, a1 = 0.f, a2 = 0.f;
#pragma unroll
    for (int cy = 0; cy < 2; cy++) {
        int yi = y0 + cy;
        if (yi >= 0 && yi < HH) {
            float wyv = cy ? wy : 1.f - wy;
            float w0 = wyv * (1.f - wx);
            float w1 = wyv * wx;
            const float* row = r2 + yi * WW;
#pragma unroll
            for (int pl = 0; pl < 3; pl++) {
                const float* rp = row + pl * HW;
                float2 e = make_float2(0.f, 0.f);
                if (bx) e = __ldg((const float2*)(rp + base));
                float vx0, vx1;
                if (ev) { vx0 = e.x; vx1 = e.y; }
                else {
                    vx0 = e.y;
                    vx1 = fixv ? __ldg(rp + xb) : 0.f;
                }
                float s = w0 * vx0 + w1 * vx1;   // out-of-range x reads 0 == zero padding
                if      (pl == 0) a0 += s;
                else if (pl == 1) a1 += s;
                else              a2 += s;
            }
        }
    }

    const float* r1 = rgb1 + (size_t)b * 3 * HW + rem;
    float c0 = r1[0], c1 = r1[HW], c2 = r1[2 * HW];

    float metric = (fabsf(c0 - a0) + fabsf(c1 - a1) + fabsf(c2 - a2)) * (1.f / 3.f);
    // metric section of output: after the 3-channel splat image
    out[(size_t)BB * 3 * HW + idx] = metric;

    float m  = fmaxf(-ALPHA * metric, -ALPHA);  // upper clip can't trigger (metric>=0)
    float em = expf(m);

    // ---- forward splat with flow_src1_to_tgt (bilinear scatter-add) ----
    const float* ft = ftgt + (size_t)b * 2 * HW + rem;
    px = (float)x + ft[0];
    py = (float)y + ft[HW];
    x0f = floorf(px); y0f = floorf(py);
    x0 = (int)x0f; y0 = (int)y0f;
    wx = px - x0f; wy = py - y0f;

    float v0 = c0 * em, v1 = c1 * em, v2 = c2 * em;
    float* accb = g_acc + (size_t)b * HW * 4;
#pragma unroll
    for (int cy = 0; cy < 2; cy++) {
#pragma unroll
        for (int cx = 0; cx < 2; cx++) {
            int xi = x0 + cx, yi = y0 + cy;
            if (xi >= 0 && xi < WW && yi >= 0 && yi < HH) {
                float w = (cx ? wx : 1.f - wx) * (cy ? wy : 1.f - wy);
                float* p = accb + (size_t)(yi * WW + xi) * 4;
                red_add_v4(p, v0 * w, v1 * w, v2 * w, em * w);
            }
        }
    }
}

__global__ __launch_bounds__(256)
void norm_kernel(float* __restrict__ out) {
    int idx = blockIdx.x * blockDim.x + threadIdx.x;
    if (idx >= NPIX) return;
    int b   = idx / HW;
    int rem = idx - b * HW;
    float4 acc = *reinterpret_cast<const float4*>(g_acc + (size_t)idx * 4);
    float inv = 1.0f / (acc.w + EPSN);
    float* o = out + (size_t)b * 3 * HW + rem;
    o[0]      = acc.x * inv;
    o[HW]     = acc.y * inv;
    o[2 * HW] = acc.z * inv;
}

extern "C" void kernel_launch(void* const* d_in, const int* in_sizes, int n_in,
                              void* d_out, int out_size) {
    const float* rgb1 = (const float*)d_in[0];
    const float* rgb2 = (const float*)d_in[1];
    const float* ftgt = (const float*)d_in[2];  // flow_src1_to_tgt
    const float* f12  = (const float*)d_in[3];  // flow_src1_to_src2
    float* out = (float*)d_out;

    void* accp = nullptr;
    cudaGetSymbolAddress(&accp, g_acc);
    cudaMemsetAsync(accp, 0, (size_t)NPIX * 4 * sizeof(float));

    int threads = 256;
    int blocks  = (NPIX + threads - 1) / threads;
    splat_kernel<<<blocks, threads>>>(rgb1, rgb2, ftgt, f12, out);
    norm_kernel<<<blocks, threads>>>(out);
}

// round 10
// speedup vs baseline: 1.6514x; 1.2114x over previous
#include <cuda_runtime.h>
#include <cstdint>

#define BB 4
#define HH 1024
#define WW 1920
#define HW (HH * WW)
#define NPIX (BB * HW)
#define ALPHA 100.0f
#define EPSN 1e-7f

#define TW 128   // tile width  (1920 = 15*128)
#define TH 32    // tile height (1024 = 32*32)
#define TY 8     // block y-threads; TH/TY = 4 rows per thread

// Interleaved accumulator: [pix][4] = {num_r, num_g, num_b, den}, 16B aligned.
__device__ __align__(16) float g_acc[(size_t)NPIX * 4];

__device__ __forceinline__ void red_add_v4(float* addr, float a, float b, float c, float d) {
    asm volatile("red.global.add.v4.f32 [%0], {%1, %2, %3, %4};"
                 :: "l"(addr), "f"(a), "f"(b), "f"(c), "f"(d) : "memory");
}

__global__ __launch_bounds__(1024, 2)
void splat_kernel(const float* __restrict__ rgb1,
                  const float* __restrict__ rgb2,
                  const float* __restrict__ ftgt,
                  const float* __restrict__ f12,
                  float* __restrict__ out) {
    int b     = blockIdx.z;
    int x     = blockIdx.x * TW + threadIdx.x;
    int ybase = blockIdx.y * TH + threadIdx.y;

    const float* r2   = rgb2 + (size_t)b * 3 * HW;
    const float* r1b  = rgb1 + (size_t)b * 3 * HW;
    const float* flb  = f12  + (size_t)b * 2 * HW;
    const float* ftb  = ftgt + (size_t)b * 2 * HW;
    float*       accb = g_acc + (size_t)b * HW * 4;
    float*       metb = out + (size_t)BB * 3 * HW + (size_t)b * HW;

#pragma unroll
    for (int i = 0; i < TH / TY; i++) {
        int y   = ybase + i * TY;
        int rem = y * WW + x;

        // ---- backwarp src2 with flow_src1_to_src2 (bilinear gather, zero outside) ----
        float px = (float)x + flb[rem];
        float py = (float)y + flb[rem + HW];
        float x0f = floorf(px), y0f = floorf(py);
        int   x0  = (int)x0f,   y0  = (int)y0f;
        float wx = px - x0f, wy = py - y0f;

        float a0 = 0.f, a1 = 0.f, a2 = 0.f;
#pragma unroll
        for (int cy = 0; cy < 2; cy++) {
#pragma unroll
            for (int cx = 0; cx < 2; cx++) {
                int xi = x0 + cx, yi = y0 + cy;
                if (xi >= 0 && xi < WW && yi >= 0 && yi < HH) {
                    float w = (cx ? wx : 1.f - wx) * (cy ? wy : 1.f - wy);
                    int o = yi * WW + xi;
                    a0 += w * __ldg(r2 + o);
                    a1 += w * __ldg(r2 + o + HW);
                    a2 += w * __ldg(r2 + o + 2 * HW);
                }
            }
        }

        float c0 = r1b[rem], c1 = r1b[rem + HW], c2 = r1b[rem + 2 * HW];

        float metric = (fabsf(c0 - a0) + fabsf(c1 - a1) + fabsf(c2 - a2)) * (1.f / 3.f);
        metb[rem] = metric;

        float m  = fmaxf(-ALPHA * metric, -ALPHA);  // upper clip can't trigger (metric>=0)
        float em = expf(m);

        // ---- forward splat with flow_src1_to_tgt (bilinear scatter-add) ----
        px = (float)x + ftb[rem];
        py = (float)y + ftb[rem + HW];
        x0f = floorf(px); y0f = floorf(py);
        x0 = (int)x0f; y0 = (int)y0f;
        wx = px - x0f; wy = py - y0f;

        float v0 = c0 * em, v1 = c1 * em, v2 = c2 * em;
#pragma unroll
        for (int cy = 0; cy < 2; cy++) {
#pragma unroll
            for (int cx = 0; cx < 2; cx++) {
                int xi = x0 + cx, yi = y0 + cy;
                if (xi >= 0 && xi < WW && yi >= 0 && yi < HH) {
                    float w = (cx ? wx : 1.f - wx) * (cy ? wy : 1.f - wy);
                    float* p = accb + (size_t)(yi * WW + xi) * 4;
                    red_add_v4(p, v0 * w, v1 * w, v2 * w, em * w);
                }
            }
        }
    }
}

__global__ __launch_bounds__(256)
void norm_kernel(float* __restrict__ out) {
    int idx = blockIdx.x * blockDim.x + threadIdx.x;
    if (idx >= NPIX) return;
    int b   = idx / HW;
    int rem = idx - b * HW;
    float4 acc = *reinterpret_cast<const float4*>(g_acc + (size_t)idx * 4);
    float inv = 1.0f / (acc.w + EPSN);
    float* o = out + (size_t)b * 3 * HW + rem;
    o[0]      = acc.x * inv;
    o[HW]     = acc.y * inv;
    o[2 * HW] = acc.z * inv;
}

extern "C" void kernel_launch(void* const* d_in, const int* in_sizes, int n_in,
                              void* d_out, int out_size) {
    const float* rgb1 = (const float*)d_in[0];
    const float* rgb2 = (const float*)d_in[1];
    const float* ftgt = (const float*)d_in[2];  // flow_src1_to_tgt
    const float* f12  = (const float*)d_in[3];  // flow_src1_to_src2
    float* out = (float*)d_out;

    void* accp = nullptr;
    cudaGetSymbolAddress(&accp, g_acc);
    cudaMemsetAsync(accp, 0, (size_t)NPIX * 4 * sizeof(float));

    dim3 block(TW, TY, 1);                        // 128 x 8 = 1024 threads
    dim3 grid(WW / TW, HH / TH, BB);              // 15 x 32 x 4 = 1920 CTAs
    splat_kernel<<<grid, block>>>(rgb1, rgb2, ftgt, f12, out);

    int threads = 256;
    int blocks  = (NPIX + threads - 1) / threads;
    norm_kernel<<<blocks, threads>>>(out);
}